// round 2
// baseline (speedup 1.0000x reference)
#include <cuda_runtime.h>
#include <cstdint>

// Partitionable-threefry dropout:
//   bits[i] = fold(threefry2x32(key=(0,42), counter=(0, i))), fold = w0 ^ w1
//   keep    = (bits >> 9) < 7549747        (== uniform < 0.9f, exact)
//   out[i]  = keep ? x[i] * (1/0.9) : 0,   cols [0,64) of each 4096-row -> 0
#define KS0 0x00000000u
#define KS1 0x0000002Au
#define KS2 (0x1BD11BDAu ^ KS0 ^ KS1)   // 0x1BD11BF0

#define KEEP_THRESH 7549747u
#define DROP_SCALE ((float)(1.0 / 0.9))

__device__ __forceinline__ uint32_t rotl32(uint32_t x, int r) {
    return __funnelshift_l(x, x, r);
}

// Full threefry2x32 block with c0 = 0, c1 = i, key (0,42); returns w0 ^ w1.
__device__ __forceinline__ uint32_t threefry_fold(uint32_t i) {
    uint32_t x0 = 0u + KS0;        // = 0
    uint32_t x1 = i + KS1;         // i + 42

#define TF_ROUND(r) do { x0 += x1; x1 = rotl32(x1, (r)); x1 ^= x0; } while (0)

    TF_ROUND(13); TF_ROUND(15); TF_ROUND(26); TF_ROUND(6);
    x0 += KS1; x1 += KS2 + 1u;
    TF_ROUND(17); TF_ROUND(29); TF_ROUND(16); TF_ROUND(24);
    x0 += KS2; x1 += KS0 + 2u;
    TF_ROUND(13); TF_ROUND(15); TF_ROUND(26); TF_ROUND(6);
    x0 += KS0; x1 += KS1 + 3u;
    TF_ROUND(17); TF_ROUND(29); TF_ROUND(16); TF_ROUND(24);
    x0 += KS1; x1 += KS2 + 4u;
    TF_ROUND(13); TF_ROUND(15); TF_ROUND(26); TF_ROUND(6);
    x0 += KS2; x1 += KS0 + 5u;

#undef TF_ROUND
    return x0 ^ x1;
}

// 8 consecutive elements per thread: two float4 loads/stores, 8 independent
// threefry chains for ILP. base is 8-aligned and 64 % 8 == 0, so the
// column-kill test (i & 4095) < 64 is uniform across the group.
__global__ void __launch_bounds__(256)
dropout_threefry_part_kernel(const float* __restrict__ x,
                             float* __restrict__ out) {
    uint32_t base = (blockIdx.x * blockDim.x + threadIdx.x) * 8u;

    const float4 a = *reinterpret_cast<const float4*>(x + base);
    const float4 b = *reinterpret_cast<const float4*>(x + base + 4u);

    const float scale = ((base & 4095u) < 64u) ? 0.0f : DROP_SCALE;

    uint32_t bits[8];
#pragma unroll
    for (int j = 0; j < 8; ++j) {
        bits[j] = threefry_fold(base + (uint32_t)j);
    }

    float4 ra, rb;
    ra.x = ((bits[0] >> 9) < KEEP_THRESH) ? a.x * scale : 0.0f;
    ra.y = ((bits[1] >> 9) < KEEP_THRESH) ? a.y * scale : 0.0f;
    ra.z = ((bits[2] >> 9) < KEEP_THRESH) ? a.z * scale : 0.0f;
    ra.w = ((bits[3] >> 9) < KEEP_THRESH) ? a.w * scale : 0.0f;
    rb.x = ((bits[4] >> 9) < KEEP_THRESH) ? b.x * scale : 0.0f;
    rb.y = ((bits[5] >> 9) < KEEP_THRESH) ? b.y * scale : 0.0f;
    rb.z = ((bits[6] >> 9) < KEEP_THRESH) ? b.z * scale : 0.0f;
    rb.w = ((bits[7] >> 9) < KEEP_THRESH) ? b.w * scale : 0.0f;

    *reinterpret_cast<float4*>(out + base) = ra;
    *reinterpret_cast<float4*>(out + base + 4u) = rb;
}

extern "C" void kernel_launch(void* const* d_in, const int* in_sizes, int n_in,
                              void* d_out, int out_size) {
    const float* x = (const float*)d_in[0];
    float* out = (float*)d_out;

    const uint32_t n = (uint32_t)out_size;   // 16384 * 4096 = 2^26
    const int threads = 256;
    const uint32_t elems_per_block = threads * 8u;
    const int blocks = (int)((n + elems_per_block - 1) / elems_per_block);

    dropout_threefry_part_kernel<<<blocks, threads>>>(x, out);
}

// round 4
// speedup vs baseline: 1.0154x; 1.0154x over previous
#include <cuda_runtime.h>
#include <cstdint>

// Partitionable-threefry dropout (exact JAX match, confirmed rel_err = 0.0):
//   bits[i] = fold(threefry2x32(key=(0,42), counter=(0,i))), fold = w0 ^ w1
//   keep    = bits < (7549747 << 9)   (== (bits>>9) < 0.9f*2^23, exact)
//   out[i]  = keep ? x[i] * (1/0.9) : 0,  cols [0,64) of each 4096-row -> 0
#define KS0 0x00000000u
#define KS1 0x0000002Au
#define KS2 (0x1BD11BDAu ^ KS0 ^ KS1)   // 0x1BD11BF0

#define KEEP_CMP 0xE6666600u            // 7549747u << 9
#define DROP_SCALE ((float)(1.0 / 0.9))

__device__ __forceinline__ uint32_t rotl32(uint32_t x, int r) {
    return __funnelshift_l(x, x, r);
}

// Force the add onto the fma pipe: IMAD r = b*one + a, with `one` opaque (==1).
__device__ __forceinline__ uint32_t fadd(uint32_t a, uint32_t b, uint32_t one) {
    uint32_t r;
    asm("mad.lo.u32 %0, %1, %2, %3;" : "=r"(r) : "r"(b), "r"(one), "r"(a));
    return r;
}

// Add compile-time constant C via IMAD (fma pipe), immediate addend.
template <uint32_t C>
__device__ __forceinline__ uint32_t faddc(uint32_t a, uint32_t one) {
    uint32_t r;
    asm("mad.lo.u32 %0, %1, %2, %3;" : "=r"(r) : "r"(a), "r"(one), "n"(C));
    return r;
}

// Full threefry2x32 block, c0 = 0, c1 = i, key (0,42); returns w0 ^ w1.
// All integer adds forced to IMAD (fma pipe); SHF/LOP3 stay on alu pipe.
__device__ __forceinline__ uint32_t threefry_fold(uint32_t i, uint32_t one) {
    // init: x0 = 0 + KS0 = 0 ; x1 = i + KS1
    uint32_t x1 = faddc<KS1>(i, one);
    // round 1 with x0 == 0 folds to a copy:
    uint32_t x0 = x1;
    x1 = rotl32(x1, 13) ^ x0;

#define TF_ROUND(r) do { x0 = fadd(x0, x1, one); x1 = rotl32(x1, (r)) ^ x0; } while (0)

    TF_ROUND(15); TF_ROUND(26); TF_ROUND(6);
    x0 = faddc<KS1>(x0, one);       x1 = faddc<KS2 + 1u>(x1, one);
    TF_ROUND(17); TF_ROUND(29); TF_ROUND(16); TF_ROUND(24);
    x0 = faddc<KS2>(x0, one);       x1 = faddc<KS0 + 2u>(x1, one);
    TF_ROUND(13); TF_ROUND(15); TF_ROUND(26); TF_ROUND(6);
    x0 = faddc<KS0>(x0, one);       x1 = faddc<KS1 + 3u>(x1, one);
    TF_ROUND(17); TF_ROUND(29); TF_ROUND(16); TF_ROUND(24);
    x0 = faddc<KS1>(x0, one);       x1 = faddc<KS2 + 4u>(x1, one);
    TF_ROUND(13); TF_ROUND(15); TF_ROUND(26); TF_ROUND(6);
    x0 = faddc<KS2>(x0, one);       x1 = faddc<KS0 + 5u>(x1, one);

#undef TF_ROUND
    return x0 ^ x1;
}

// 8 consecutive elements per thread: two float4 loads/stores, 8 independent
// threefry chains for ILP. base is 8-aligned and 64 % 8 == 0, so the
// column-kill test (i & 4095) < 64 is uniform across the group.
__global__ void __launch_bounds__(256)
dropout_threefry_part_kernel(const float* __restrict__ x,
                             float* __restrict__ out,
                             uint32_t one) {
    uint32_t base = (blockIdx.x * blockDim.x + threadIdx.x) * 8u;

    const float4 a = *reinterpret_cast<const float4*>(x + base);
    const float4 b = *reinterpret_cast<const float4*>(x + base + 4u);

    const float scale = ((base & 4095u) < 64u) ? 0.0f : DROP_SCALE;

    uint32_t bits[8];
#pragma unroll
    for (int j = 0; j < 8; ++j) {
        bits[j] = threefry_fold(base + (uint32_t)j, one);
    }

    float4 ra, rb;
    ra.x = (bits[0] < KEEP_CMP) ? a.x * scale : 0.0f;
    ra.y = (bits[1] < KEEP_CMP) ? a.y * scale : 0.0f;
    ra.z = (bits[2] < KEEP_CMP) ? a.z * scale : 0.0f;
    ra.w = (bits[3] < KEEP_CMP) ? a.w * scale : 0.0f;
    rb.x = (bits[4] < KEEP_CMP) ? b.x * scale : 0.0f;
    rb.y = (bits[5] < KEEP_CMP) ? b.y * scale : 0.0f;
    rb.z = (bits[6] < KEEP_CMP) ? b.z * scale : 0.0f;
    rb.w = (bits[7] < KEEP_CMP) ? b.w * scale : 0.0f;

    *reinterpret_cast<float4*>(out + base) = ra;
    *reinterpret_cast<float4*>(out + base + 4u) = rb;
}

extern "C" void kernel_launch(void* const* d_in, const int* in_sizes, int n_in,
                              void* d_out, int out_size) {
    const float* x = (const float*)d_in[0];
    float* out = (float*)d_out;

    const uint32_t n = (uint32_t)out_size;   // 16384 * 4096 = 2^26
    const int threads = 256;
    const uint32_t elems_per_block = threads * 8u;
    const int blocks = (int)((n + elems_per_block - 1) / elems_per_block);

    dropout_threefry_part_kernel<<<blocks, threads>>>(x, out, 1u);
}